// round 11
// baseline (speedup 1.0000x reference)
#include <cuda_runtime.h>
#include <cstdint>
#include <cstddef>

#define Dm   512
#define Bm_  16
#define Sm   4096
#define G3   1536
#define NGRP 8           // independent scan groups (2 batches each)
#define GCTA 16          // CTAs per group = cluster size
#define BPG  2           // batches per group
#define DPC  32          // h-dims per CTA (96 Wh columns)
#define NBLK (NGRP * GCTA)
#define NTHR 256

// Scratch (device globals: allocation-free per harness rules)
__device__ float g_gi[(size_t)Bm_ * Sm * G3];   // [b][t][1536]
__device__ float g_rnn[(size_t)Bm_ * Sm * Dm];  // [b][t][512]

// ---------------------------------------------------------------------------
// SGEMM: C[M,N] = A[M,K] @ B[K,N] + bias[N]   (BM=128, BN=64, BK=16)
// ---------------------------------------------------------------------------
__global__ void __launch_bounds__(256) sgemm_bias(
    const float* __restrict__ A, const float* __restrict__ Bmat,
    const float* __restrict__ bias, float* __restrict__ C,
    int M, int N, int K)
{
    __shared__ float As[16][132];
    __shared__ float Bs[16][64];

    const int tid = threadIdx.x;
    const int tx = tid & 15;
    const int ty = tid >> 4;
    const int m0 = blockIdx.y * 128;
    const int n0 = blockIdx.x * 64;

    const int a_row = tid >> 2;
    const int a_kq  = (tid & 3) * 4;

    float acc[8][4];
#pragma unroll
    for (int i = 0; i < 8; ++i)
#pragma unroll
        for (int j = 0; j < 4; ++j) acc[i][j] = 0.f;

    for (int k0 = 0; k0 < K; k0 += 16) {
#pragma unroll
        for (int j = 0; j < 2; ++j) {
            int row = a_row + j * 64;
            float4 v = *(const float4*)(A + (size_t)(m0 + row) * K + k0 + a_kq);
            As[a_kq + 0][row] = v.x;
            As[a_kq + 1][row] = v.y;
            As[a_kq + 2][row] = v.z;
            As[a_kq + 3][row] = v.w;
        }
        {
            float4 v = *(const float4*)(Bmat + (size_t)(k0 + ty) * N + n0 + tx * 4);
            *(float4*)&Bs[ty][tx * 4] = v;
        }
        __syncthreads();
#pragma unroll
        for (int kk = 0; kk < 16; ++kk) {
            float a[8], b[4];
            *(float4*)&a[0] = *(const float4*)&As[kk][ty * 8];
            *(float4*)&a[4] = *(const float4*)&As[kk][ty * 8 + 4];
            *(float4*)&b[0] = *(const float4*)&Bs[kk][tx * 4];
#pragma unroll
            for (int i = 0; i < 8; ++i)
#pragma unroll
                for (int j = 0; j < 4; ++j)
                    acc[i][j] += a[i] * b[j];
        }
        __syncthreads();
    }

    float4 bv = *(const float4*)(bias + n0 + tx * 4);
#pragma unroll
    for (int i = 0; i < 8; ++i) {
        float4 o;
        o.x = acc[i][0] + bv.x;
        o.y = acc[i][1] + bv.y;
        o.z = acc[i][2] + bv.z;
        o.w = acc[i][3] + bv.w;
        *(float4*)(C + (size_t)(m0 + ty * 8 + i) * N + n0 + tx * 4) = o;
    }
}

// ---------------------------------------------------------------------------
// Persistent GRU scan with DSMEM clusters.
// 8 clusters of 16 CTAs; cluster = one group of 2 batches over all 512 dims.
// CTA owns 32 dims: 96 Wh cols in REGISTERS (12 cols/warp x 16 k = 192 regs).
// Per step: k-loop on local SMEM h2 -> shfl reduce -> gates -> broadcast h
// to all 16 cluster CTAs via st.shared::cluster -> barrier.cluster.
// No global H, no atomics.
// ---------------------------------------------------------------------------
__global__ void __launch_bounds__(NTHR, 1) gru_scan(
    const float* __restrict__ Wh, const float* __restrict__ bhn)
{
    __shared__ unsigned long long h2[2][Dm];     // (h[b0],h[b1]) pairs, ping-pong
    __shared__ unsigned long long stage[DPC];    // this CTA's new h pairs
    __shared__ float2 red[96 * 8];               // [col][8] 8-lane partials

    const int tid = threadIdx.x;
    const int warp = tid >> 5, lane = tid & 31;

    unsigned rank;
    asm("mov.u32 %0, %%cluster_ctarank;" : "=r"(rank));
    const int grp = blockIdx.x >> 4;
    const int d0  = (int)rank * DPC;
    const int b0  = grp * BPG;

    // ---- one-time: 12 cols x 16 k weights into registers ----
    // col cc = 12*warp + i -> gate = cc/32, dim = cc%32 ; k = lane + 32*j
    float w[12][16];
#pragma unroll
    for (int i = 0; i < 12; ++i) {
        int cc = 12 * warp + i;
        int gate = cc >> 5, dim = cc & 31;
        const float* wp = Wh + (size_t)lane * G3 + gate * Dm + d0 + dim;
#pragma unroll
        for (int j = 0; j < 16; ++j)
            w[i][j] = __ldg(wp + (size_t)j * 32 * G3);
    }

    const int dloc = tid >> 1, gb = tid & 1;    // gate mapping (tid<64)
    float my_bhn = 0.f;
    if (tid < 64) my_bhn = bhn[d0 + dloc];

    // init h0 = 0 (own buffer only; each CTA reads own smem)
    for (int i = tid; i < Dm; i += NTHR) h2[0][i] = 0ull;
    __syncthreads();

    const unsigned h2_base = (unsigned)__cvta_generic_to_shared(&h2[0][0]);

    // cluster rendezvous before any remote traffic
    asm volatile("barrier.cluster.arrive.aligned;" ::: "memory");
    asm volatile("barrier.cluster.wait.aligned;"   ::: "memory");

    for (int t = 0; t < Sm; ++t) {
        const int cur = t & 1, nxt = cur ^ 1;

        // gi prefetch (DRAM latency hidden under k-loop)
        float gir = 0.f, giz = 0.f, gin = 0.f;
        if (tid < 64) {
            const float* gp = g_gi + ((size_t)(b0 + gb) * Sm + t) * G3 + d0 + dloc;
            gir = __ldg(gp); giz = __ldg(gp + Dm); gin = __ldg(gp + 2 * Dm);
        }

        // ---- k-loop: register weights x local-SMEM h pairs ----
        unsigned long long acc[12];
#pragma unroll
        for (int i = 0; i < 12; ++i) acc[i] = 0ull;

#pragma unroll
        for (int j = 0; j < 16; ++j) {
            unsigned long long hv = h2[cur][lane + 32 * j];
#pragma unroll
            for (int i = 0; i < 12; ++i) {
                unsigned long long wd;
                asm("mov.b64 %0, {%1, %1};" : "=l"(wd) : "f"(w[i][j]));
                asm("fma.rn.f32x2 %0, %1, %2, %0;"
                    : "+l"(acc[i]) : "l"(wd), "l"(hv));
            }
        }

        // ---- reduce over lanes: xor16, xor8 -> lanes 0-7 hold 8-way partials
        float p0[12], p1[12];
#pragma unroll
        for (int i = 0; i < 12; ++i) {
            asm("mov.b64 {%0,%1}, %2;" : "=f"(p0[i]), "=f"(p1[i]) : "l"(acc[i]));
            p0[i] += __shfl_xor_sync(0xffffffffu, p0[i], 16);
            p1[i] += __shfl_xor_sync(0xffffffffu, p1[i], 16);
            p0[i] += __shfl_xor_sync(0xffffffffu, p0[i], 8);
            p1[i] += __shfl_xor_sync(0xffffffffu, p1[i], 8);
        }
        if (lane < 8) {
#pragma unroll
            for (int i = 0; i < 12; ++i)
                red[(12 * warp + i) * 8 + lane] = make_float2(p0[i], p1[i]);
        }
        __syncthreads();

        // ---- gates: 64 threads = 32 dims x 2 batches ----
        if (tid < 64) {
            float gh[3];
#pragma unroll
            for (int g3 = 0; g3 < 3; ++g3) {
                const float2* rp = &red[(g3 * 32 + dloc) * 8];
                float s = 0.f;
#pragma unroll
                for (int l = 0; l < 8; ++l) {
                    float2 v = rp[l];
                    s += gb ? v.y : v.x;
                }
                gh[g3] = s;
            }
            unsigned long long hv = h2[cur][d0 + dloc];
            float hl, hh;
            asm("mov.b64 {%0,%1}, %2;" : "=f"(hl), "=f"(hh) : "l"(hv));
            float hold = gb ? hh : hl;

            float r = 1.f / (1.f + __expf(-(gir + gh[0])));
            float z = 1.f / (1.f + __expf(-(giz + gh[1])));
            float n = tanhf(gin + r * (gh[2] + my_bhn));
            float hnew = (1.f - z) * n + z * hold;
            ((float*)&stage[dloc])[gb] = hnew;
            g_rnn[((size_t)(b0 + gb) * Sm + t) * Dm + d0 + dloc] = hnew;
        }
        __syncthreads();

        // ---- broadcast own 32 h-pairs to all 16 cluster CTAs ----
#pragma unroll
        for (int r = 0; r < 2; ++r) {
            int idx = tid + r * NTHR;        // 0..511
            int p   = idx >> 5;              // peer rank 0..15
            int dim = idx & 31;
            unsigned long long v = stage[dim];
            unsigned laddr = h2_base + (unsigned)((nxt * Dm + d0 + dim) * 8);
            unsigned raddr;
            asm("mapa.shared::cluster.u32 %0, %1, %2;"
                : "=r"(raddr) : "r"(laddr), "r"(p));
            asm volatile("st.shared::cluster.b64 [%0], %1;"
                         :: "r"(raddr), "l"(v) : "memory");
        }

        // ---- cluster barrier: release own stores / acquire peers' ----
        asm volatile("barrier.cluster.arrive.aligned;" ::: "memory");
        asm volatile("barrier.cluster.wait.aligned;"   ::: "memory");
    }
}

// ---------------------------------------------------------------------------
extern "C" void kernel_launch(void* const* d_in, const int* in_sizes, int n_in,
                              void* d_out, int out_size)
{
    const float* x   = (const float*)d_in[0];
    const float* Wi  = (const float*)d_in[1];
    const float* bi  = (const float*)d_in[2];
    const float* Wh  = (const float*)d_in[3];
    const float* bhn = (const float*)d_in[4];
    const float* Wo  = (const float*)d_in[5];
    const float* bo  = (const float*)d_in[6];
    float* out = (float*)d_out;

    void* gi_ptr = nullptr;
    void* rnn_ptr = nullptr;
    cudaGetSymbolAddress(&gi_ptr, g_gi);
    cudaGetSymbolAddress(&rnn_ptr, g_rnn);

    dim3 g1(G3 / 64, (Bm_ * Sm) / 128);
    sgemm_bias<<<g1, 256>>>(x, Wi, bi, (float*)gi_ptr, Bm_ * Sm, G3, Dm);

    // scan: 8 clusters of 16 CTAs (nonportable cluster size)
    cudaFuncSetAttribute(gru_scan,
                         cudaFuncAttributeNonPortableClusterSizeAllowed, 1);
    cudaLaunchConfig_t cfg = {};
    cfg.gridDim  = dim3(NBLK, 1, 1);
    cfg.blockDim = dim3(NTHR, 1, 1);
    cudaLaunchAttribute attrs[1];
    attrs[0].id = cudaLaunchAttributeClusterDimension;
    attrs[0].val.clusterDim.x = GCTA;
    attrs[0].val.clusterDim.y = 1;
    attrs[0].val.clusterDim.z = 1;
    cfg.attrs = attrs;
    cfg.numAttrs = 1;
    cudaLaunchKernelEx(&cfg, gru_scan, Wh, bhn);

    dim3 g2(Dm / 64, (Bm_ * Sm) / 128);
    sgemm_bias<<<g2, 256>>>((const float*)rnn_ptr, Wo, bo, out, Bm_ * Sm, Dm, Dm);
}

// round 12
// speedup vs baseline: 1.1084x; 1.1084x over previous
#include <cuda_runtime.h>
#include <cstdint>
#include <cstddef>

#define Dm   512
#define Bm_  16
#define Sm   4096
#define G3   1536
#define NGRP 4           // independent scan groups (4 batches each)
#define GCTA 32          // CTAs per group
#define BPG  4           // batches per group
#define DPC  16          // h-dims per CTA (48 Wh columns)
#define NBLK (NGRP * GCTA)
#define NTHR 256

// Scratch (device globals: allocation-free per harness rules)
__device__ float    g_gi[(size_t)Bm_ * Sm * G3];   // [b][t][1536]
__device__ float    g_rnn[(size_t)Bm_ * Sm * Dm];  // [b][t][512]
__device__ float    g_h[2][NGRP][Dm][BPG];         // ping-pong H per group
__device__ unsigned g_cnt[NGRP * 32];              // per-group counters, 128B apart

__global__ void init_state()
{
    int tid = blockIdx.x * blockDim.x + threadIdx.x;
    if (tid < NGRP * 32) g_cnt[tid] = 0u;
    if (tid < NGRP * Dm * BPG) ((float*)g_h)[tid] = 0.f;   // zero g_h[0]
}

__device__ __forceinline__ unsigned ld_acq(const unsigned* p)
{
    unsigned v;
    asm volatile("ld.acquire.gpu.u32 %0, [%1];" : "=r"(v) : "l"(p) : "memory");
    return v;
}

__device__ __forceinline__ void ffma2(unsigned long long& d,
                                      unsigned long long a,
                                      unsigned long long b)
{
    asm("fma.rn.f32x2 %0, %1, %2, %0;" : "+l"(d) : "l"(a), "l"(b));
}

// pack (w,w) once, then two packed fp32x2 FMAs into separate accumulators
__device__ __forceinline__ void ffma2_dual(unsigned long long& dA,
                                           unsigned long long& dB,
                                           float w,
                                           unsigned long long hA,
                                           unsigned long long hB)
{
    unsigned long long wd;
    asm("mov.b64 %0, {%1, %1};" : "=l"(wd) : "f"(w));
    asm("fma.rn.f32x2 %0, %1, %2, %0;" : "+l"(dA) : "l"(wd), "l"(hA));
    asm("fma.rn.f32x2 %0, %1, %2, %0;" : "+l"(dB) : "l"(wd), "l"(hB));
}

// ---------------------------------------------------------------------------
// SGEMM with packed f32x2 math: C = A @ B + bias   (BM=128, BN=64, BK=16)
// Accumulators are 8x2 f32x2 pairs (n-adjacent), halving fma-pipe ops.
// ---------------------------------------------------------------------------
__global__ void __launch_bounds__(256) sgemm_bias(
    const float* __restrict__ A, const float* __restrict__ Bmat,
    const float* __restrict__ bias, float* __restrict__ C,
    int M, int N, int K)
{
    __shared__ float As[16][132];
    __shared__ float Bs[16][64];

    const int tid = threadIdx.x;
    const int tx = tid & 15;
    const int ty = tid >> 4;
    const int m0 = blockIdx.y * 128;
    const int n0 = blockIdx.x * 64;

    const int a_row = tid >> 2;
    const int a_kq  = (tid & 3) * 4;

    unsigned long long accp[8][2];
#pragma unroll
    for (int i = 0; i < 8; ++i) { accp[i][0] = 0ull; accp[i][1] = 0ull; }

    for (int k0 = 0; k0 < K; k0 += 16) {
#pragma unroll
        for (int j = 0; j < 2; ++j) {
            int row = a_row + j * 64;
            float4 v = *(const float4*)(A + (size_t)(m0 + row) * K + k0 + a_kq);
            As[a_kq + 0][row] = v.x;
            As[a_kq + 1][row] = v.y;
            As[a_kq + 2][row] = v.z;
            As[a_kq + 3][row] = v.w;
        }
        {
            float4 v = *(const float4*)(Bmat + (size_t)(k0 + ty) * N + n0 + tx * 4);
            *(float4*)&Bs[ty][tx * 4] = v;
        }
        __syncthreads();
#pragma unroll
        for (int kk = 0; kk < 16; ++kk) {
            float a[8];
            *(float4*)&a[0] = *(const float4*)&As[kk][ty * 8];
            *(float4*)&a[4] = *(const float4*)&As[kk][ty * 8 + 4];
            ulonglong2 bp = *(const ulonglong2*)&Bs[kk][tx * 4];
#pragma unroll
            for (int i = 0; i < 8; ++i) {
                unsigned long long ad;
                asm("mov.b64 %0, {%1, %1};" : "=l"(ad) : "f"(a[i]));
                ffma2(accp[i][0], ad, bp.x);
                ffma2(accp[i][1], ad, bp.y);
            }
        }
        __syncthreads();
    }

    float4 bv = *(const float4*)(bias + n0 + tx * 4);
#pragma unroll
    for (int i = 0; i < 8; ++i) {
        float4 o;
        asm("mov.b64 {%0,%1}, %2;" : "=f"(o.x), "=f"(o.y) : "l"(accp[i][0]));
        asm("mov.b64 {%0,%1}, %2;" : "=f"(o.z), "=f"(o.w) : "l"(accp[i][1]));
        o.x += bv.x; o.y += bv.y; o.z += bv.z; o.w += bv.w;
        *(float4*)(C + (size_t)(m0 + ty * 8 + i) * N + n0 + tx * 4) = o;
    }
}

// ---------------------------------------------------------------------------
// Persistent GRU scan (R10 structure): weights in registers (96/thread),
// H read directly from global via coalesced .cg v2.u64 (no SMEM staging),
// hold in register, gi prefetched one step ahead, early-arrival barrier.
// 4 independent groups x 32 CTAs; CTA owns 16 dims x 4 batches.
// ---------------------------------------------------------------------------
__global__ void __launch_bounds__(NTHR, 1) gru_scan(
    const float* __restrict__ Wh, const float* __restrict__ bhn)
{
    __shared__ float red[48 * BPG * 8]; // [cc][b][8] 8-way partials

    const int tid = threadIdx.x;
    const int bid = blockIdx.x;
    const int grp = bid >> 5;
    const int cid = bid & 31;
    const int d0  = cid * DPC;
    const int b0  = grp * BPG;

    const int warp = tid >> 5, lane = tid & 31;

    // ---- one-time: this thread's 96 weights into registers ----
    // col cc = 6*warp + i -> gate = cc/16, dim = cc%16 ; k = lane + 32*j
    float w[6][16];
#pragma unroll
    for (int i = 0; i < 6; ++i) {
        int cc = 6 * warp + i;
        int gate = cc >> 4, dim = cc & 15;
        const float* wp = Wh + (size_t)gate * Dm + d0 + dim + (size_t)lane * G3;
#pragma unroll
        for (int j = 0; j < 16; ++j)
            w[i][j] = __ldg(wp + (size_t)j * 32 * G3);
    }

    const int dloc = tid >> 2, gb = tid & 3;   // gate mapping (tid<64)
    float my_bhn = 0.f;
    if (tid < 64) my_bhn = bhn[d0 + dloc];

    unsigned* cnt = &g_cnt[grp * 32];
    unsigned target = 0;

    // hold register (h(0)=0) and gi prefetch for t=0
    float hold = 0.f;
    float gir = 0.f, giz = 0.f, gin = 0.f;
    if (tid < 64) {
        const float* gp = g_gi + ((size_t)(b0 + gb) * Sm + 0) * G3 + d0 + dloc;
        gir = __ldg(gp); giz = __ldg(gp + Dm); gin = __ldg(gp + 2 * Dm);
    }

    for (int t = 0; t < Sm; ++t) {
        const float* Hc = &g_h[t & 1][grp][0][0];
        float* Hn = &g_h[(t & 1) ^ 1][grp][0][0];

        // ---- k-loop: register weights x direct-global H pairs ----
        unsigned long long accA[6], accB[6];
#pragma unroll
        for (int i = 0; i < 6; ++i) { accA[i] = 0ull; accB[i] = 0ull; }

#pragma unroll
        for (int j = 0; j < 16; ++j) {
            int k = lane + 32 * j;
            unsigned long long ha, hb;  // (b0,b1), (b2,b3)
            asm volatile("ld.global.cg.v2.u64 {%0,%1}, [%2];"
                         : "=l"(ha), "=l"(hb) : "l"(&Hc[k * BPG]));
#pragma unroll
            for (int i = 0; i < 6; ++i)
                ffma2_dual(accA[i], accB[i], w[i][j], ha, hb);
        }

        // ---- reduce over lanes: xor16, xor8 -> lanes 0-7 hold 8-way partials
        float pA0[6], pA1[6], pB0[6], pB1[6];
#pragma unroll
        for (int i = 0; i < 6; ++i) {
            asm("mov.b64 {%0,%1}, %2;" : "=f"(pA0[i]), "=f"(pA1[i]) : "l"(accA[i]));
            asm("mov.b64 {%0,%1}, %2;" : "=f"(pB0[i]), "=f"(pB1[i]) : "l"(accB[i]));
            pA0[i] += __shfl_xor_sync(0xffffffffu, pA0[i], 16);
            pA1[i] += __shfl_xor_sync(0xffffffffu, pA1[i], 16);
            pB0[i] += __shfl_xor_sync(0xffffffffu, pB0[i], 16);
            pB1[i] += __shfl_xor_sync(0xffffffffu, pB1[i], 16);
            pA0[i] += __shfl_xor_sync(0xffffffffu, pA0[i], 8);
            pA1[i] += __shfl_xor_sync(0xffffffffu, pA1[i], 8);
            pB0[i] += __shfl_xor_sync(0xffffffffu, pB0[i], 8);
            pB1[i] += __shfl_xor_sync(0xffffffffu, pB1[i], 8);
        }
        if (lane < 8) {
#pragma unroll
            for (int i = 0; i < 6; ++i) {
                int cc = 6 * warp + i;
                red[(cc * BPG + 0) * 8 + lane] = pA0[i];
                red[(cc * BPG + 1) * 8 + lane] = pA1[i];
                red[(cc * BPG + 2) * 8 + lane] = pB0[i];
                red[(cc * BPG + 3) * 8 + lane] = pB1[i];
            }
        }
        __syncthreads();

        // ---- gates (64 threads: 16 dims x 4 batches) ----
        if (tid < 64) {
            float gh[3];
#pragma unroll
            for (int g3 = 0; g3 < 3; ++g3) {
                const float* rp = &red[((g3 * 16 + dloc) * BPG + gb) * 8];
                float s = 0.f;
#pragma unroll
                for (int l = 0; l < 8; ++l) s += rp[l];
                gh[g3] = s;
            }
            float r = 1.f / (1.f + __expf(-(gir + gh[0])));
            float z = 1.f / (1.f + __expf(-(giz + gh[1])));
            float n = tanhf(gin + r * (gh[2] + my_bhn));
            float hnew = (1.f - z) * n + z * hold;
            hold = hnew;                                   // own h stays in reg
            Hn[(d0 + dloc) * BPG + gb] = hnew;             // publish for peers
            g_rnn[((size_t)(b0 + gb) * Sm + t) * Dm + d0 + dloc] = hnew;

            // prefetch gi for t+1 (full-step latency cover)
            if (t + 1 < Sm) {
                const float* gp = g_gi
                    + ((size_t)(b0 + gb) * Sm + (t + 1)) * G3 + d0 + dloc;
                gir = __ldg(gp); giz = __ldg(gp + Dm); gin = __ldg(gp + 2 * Dm);
            }
        }

        // ---- early arrival: gate warps sync, tid0 fences + arrives ----
        if (tid < 64)
            asm volatile("bar.sync 1, 64;" ::: "memory");
        target += GCTA;
        if (tid == 0) {
            __threadfence();
            atomicAdd(cnt, 1u);
            while (ld_acq(cnt) < target) { }
        }
        __syncthreads();
    }
}

// ---------------------------------------------------------------------------
extern "C" void kernel_launch(void* const* d_in, const int* in_sizes, int n_in,
                              void* d_out, int out_size)
{
    const float* x   = (const float*)d_in[0];
    const float* Wi  = (const float*)d_in[1];
    const float* bi  = (const float*)d_in[2];
    const float* Wh  = (const float*)d_in[3];
    const float* bhn = (const float*)d_in[4];
    const float* Wo  = (const float*)d_in[5];
    const float* bo  = (const float*)d_in[6];
    float* out = (float*)d_out;

    void* gi_ptr = nullptr;
    void* rnn_ptr = nullptr;
    cudaGetSymbolAddress(&gi_ptr, g_gi);
    cudaGetSymbolAddress(&rnn_ptr, g_rnn);

    init_state<<<32, 256>>>();

    dim3 g1(G3 / 64, (Bm_ * Sm) / 128);
    sgemm_bias<<<g1, 256>>>(x, Wi, bi, (float*)gi_ptr, Bm_ * Sm, G3, Dm);

    gru_scan<<<NBLK, NTHR>>>(Wh, bhn);

    dim3 g2(Dm / 64, (Bm_ * Sm) / 128);
    sgemm_bias<<<g2, 256>>>((const float*)rnn_ptr, Wo, bo, out, Bm_ * Sm, Dm, Dm);
}

// round 14
// speedup vs baseline: 1.3779x; 1.2431x over previous
#include <cuda_runtime.h>
#include <cstdint>
#include <cstddef>

#define Dm   512
#define Bm_  16
#define Sm   4096
#define G3   1536
#define NGRP 4           // independent scan groups (4 batches each)
#define GCTA 32          // CTAs per group
#define BPG  4           // batches per group
#define DPC  16          // h-dims per CTA (48 Wh columns)
#define NBLK (NGRP * GCTA)
#define NTHR 256

// Scratch (device globals: allocation-free per harness rules)
__device__ float    g_gi[(size_t)Bm_ * Sm * G3];   // [b][t][1536]
__device__ float    g_rnn[(size_t)Bm_ * Sm * Dm];  // [b][t][512]
__device__ float    g_h[2][NGRP][Dm][BPG];         // ping-pong H per group
__device__ unsigned g_cnt[NGRP * 32];              // per-group counters, 128B apart

__global__ void init_state()
{
    int tid = blockIdx.x * blockDim.x + threadIdx.x;
    if (tid < NGRP * 32) g_cnt[tid] = 0u;
    if (tid < NGRP * Dm * BPG) ((float*)g_h)[tid] = 0.f;   // zero g_h[0]
}

__device__ __forceinline__ unsigned ld_acq(const unsigned* p)
{
    unsigned v;
    asm volatile("ld.acquire.gpu.u32 %0, [%1];" : "=r"(v) : "l"(p) : "memory");
    return v;
}

__device__ __forceinline__ float cvt_tf32(float x)
{
    unsigned u;
    asm("cvt.rna.tf32.f32 %0, %1;" : "=r"(u) : "f"(x));
    return __uint_as_float(u);
}

// pack (w,w) once, then two packed fp32x2 FMAs into separate accumulators
__device__ __forceinline__ void ffma2_dual(unsigned long long& dA,
                                           unsigned long long& dB,
                                           float w,
                                           unsigned long long hA,
                                           unsigned long long hB)
{
    unsigned long long wd;
    asm("mov.b64 %0, {%1, %1};" : "=l"(wd) : "f"(w));
    asm("fma.rn.f32x2 %0, %1, %2, %0;" : "+l"(dA) : "l"(wd), "l"(hA));
    asm("fma.rn.f32x2 %0, %1, %2, %0;" : "+l"(dB) : "l"(wd), "l"(hB));
}

// ---------------------------------------------------------------------------
// tf32 tensor-core GEMM: C[M,N] = A[M,K] @ B[K,N] + bias[N]
// BM=128, BN=64, BK=32; 8 warps = 2(M) x 4(N); warp tile 64x16 = 4x2 mma frags
// A staged [k][m] stride 132; B staged [k][n] stride 72 (frag LDS conflict-free)
// ---------------------------------------------------------------------------
__global__ void __launch_bounds__(256) tf32_gemm_bias(
    const float* __restrict__ A, const float* __restrict__ Bmat,
    const float* __restrict__ bias, float* __restrict__ C,
    int M, int N, int K)
{
    __shared__ float As[32 * 132];   // [k][m]
    __shared__ float Bs[32 * 72];    // [k][n]

    const int tid = threadIdx.x;
    const int warp = tid >> 5, lane = tid & 31;
    const int wm = warp >> 2, wn = warp & 3;
    const int m0 = blockIdx.y * 128;
    const int n0 = blockIdx.x * 64;

    const int gid = lane >> 2;       // 0..7
    const int qid = lane & 3;        // 0..3

    const int a_row = tid >> 2;          // 0..63
    const int a_kq  = (tid & 3) * 4;     // 0,4,8,12

    float d[4][2][4];
#pragma unroll
    for (int mt = 0; mt < 4; ++mt)
#pragma unroll
        for (int nt = 0; nt < 2; ++nt)
#pragma unroll
            for (int i = 0; i < 4; ++i) d[mt][nt][i] = 0.f;

    for (int k0 = 0; k0 < K; k0 += 32) {
        // A tile 128x32 -> As[k][m] (transpose scatter, tf32-rounded)
#pragma unroll
        for (int rr = 0; rr < 2; ++rr) {
#pragma unroll
            for (int kk = 0; kk < 2; ++kk) {
                int row = a_row + rr * 64;
                int kq  = a_kq + kk * 16;
                float4 v = *(const float4*)(A + (size_t)(m0 + row) * K + k0 + kq);
                As[(kq + 0) * 132 + row] = cvt_tf32(v.x);
                As[(kq + 1) * 132 + row] = cvt_tf32(v.y);
                As[(kq + 2) * 132 + row] = cvt_tf32(v.z);
                As[(kq + 3) * 132 + row] = cvt_tf32(v.w);
            }
        }
        // B tile 32x64 -> Bs[k][n] (tf32-rounded)
        {
            int r  = tid >> 4;            // 0..15
            int cq = (tid & 15) * 4;
#pragma unroll
            for (int i = 0; i < 2; ++i) {
                int row = r + i * 16;
                float4 v = *(const float4*)(Bmat + (size_t)(k0 + row) * N + n0 + cq);
                float4 tv;
                tv.x = cvt_tf32(v.x); tv.y = cvt_tf32(v.y);
                tv.z = cvt_tf32(v.z); tv.w = cvt_tf32(v.w);
                *(float4*)&Bs[row * 72 + cq] = tv;
            }
        }
        __syncthreads();

#pragma unroll
        for (int ks = 0; ks < 4; ++ks) {
            const int kb = ks * 8;
            unsigned bf0[2], bf1[2];
#pragma unroll
            for (int nt = 0; nt < 2; ++nt) {
                int n = wn * 16 + nt * 8 + gid;
                bf0[nt] = __float_as_uint(Bs[(kb + qid) * 72 + n]);
                bf1[nt] = __float_as_uint(Bs[(kb + qid + 4) * 72 + n]);
            }
#pragma unroll
            for (int mt = 0; mt < 4; ++mt) {
                int m = wm * 64 + mt * 16 + gid;
                unsigned a0 = __float_as_uint(As[(kb + qid) * 132 + m]);
                unsigned a1 = __float_as_uint(As[(kb + qid) * 132 + m + 8]);
                unsigned a2 = __float_as_uint(As[(kb + qid + 4) * 132 + m]);
                unsigned a3 = __float_as_uint(As[(kb + qid + 4) * 132 + m + 8]);
#pragma unroll
                for (int nt = 0; nt < 2; ++nt) {
                    asm volatile(
                        "mma.sync.aligned.m16n8k8.row.col.f32.tf32.tf32.f32 "
                        "{%0,%1,%2,%3}, {%4,%5,%6,%7}, {%8,%9}, {%0,%1,%2,%3};"
                        : "+f"(d[mt][nt][0]), "+f"(d[mt][nt][1]),
                          "+f"(d[mt][nt][2]), "+f"(d[mt][nt][3])
                        : "r"(a0), "r"(a1), "r"(a2), "r"(a3),
                          "r"(bf0[nt]), "r"(bf1[nt]));
                }
            }
        }
        __syncthreads();
    }

    // epilogue: bias add + store (float2 per frag-row)
#pragma unroll
    for (int mt = 0; mt < 4; ++mt) {
        int m = m0 + wm * 64 + mt * 16 + gid;
#pragma unroll
        for (int nt = 0; nt < 2; ++nt) {
            int n = n0 + wn * 16 + nt * 8 + qid * 2;
            float2 bv = *(const float2*)(bias + n);
            float2 o0 = make_float2(d[mt][nt][0] + bv.x, d[mt][nt][1] + bv.y);
            float2 o1 = make_float2(d[mt][nt][2] + bv.x, d[mt][nt][3] + bv.y);
            *(float2*)(C + (size_t)m * N + n) = o0;
            *(float2*)(C + (size_t)(m + 8) * N + n) = o1;
        }
    }
}

// ---------------------------------------------------------------------------
// Persistent GRU scan (R10, best measured): weights in REGISTERS
// (96 floats/thread); SMEM carries H (8KB staged once/step) + partials.
// 4 independent groups x 32 CTAs; CTA owns 16 dims x 4 batches.
// ---------------------------------------------------------------------------
__global__ void __launch_bounds__(NTHR, 1) gru_scan(
    const float* __restrict__ Wh, const float* __restrict__ bhn)
{
    __shared__ float2 hA[Dm];            // (h[b0], h[b1])[k]
    __shared__ float2 hB[Dm];            // (h[b2], h[b3])[k]
    __shared__ float  red[48 * BPG * 8]; // [cc][b][8] 8-way partials

    const int tid = threadIdx.x;
    const int bid = blockIdx.x;
    const int grp = bid >> 5;
    const int cid = bid & 31;
    const int d0  = cid * DPC;
    const int b0  = grp * BPG;

    const int warp = tid >> 5, lane = tid & 31;

    // one-time: this thread's 96 weights into registers
    float w[6][16];
#pragma unroll
    for (int i = 0; i < 6; ++i) {
        int cc = 6 * warp + i;
        int gate = cc >> 4, dim = cc & 15;
        const float* wp = Wh + (size_t)gate * Dm + d0 + dim + (size_t)lane * G3;
#pragma unroll
        for (int j = 0; j < 16; ++j)
            w[i][j] = __ldg(wp + (size_t)j * 32 * G3);
    }

    const int dloc = tid >> 2, gb = tid & 3;   // gate mapping (tid<64)
    float my_bhn = 0.f;
    if (tid < 64) my_bhn = bhn[d0 + dloc];

    unsigned* cnt = &g_cnt[grp * 32];
    unsigned target = 0;

    for (int t = 0; t < Sm; ++t) {
        const float* Hc = &g_h[t & 1][grp][0][0];
        float* Hn = &g_h[(t & 1) ^ 1][grp][0][0];

        // gi prefetch (independent of barrier)
        float gir = 0.f, giz = 0.f, gin = 0.f;
        float hold = 0.f;
        if (tid < 64) {
            const float* gp = g_gi + ((size_t)(b0 + gb) * Sm + t) * G3 + d0 + dloc;
            gir = __ldg(gp); giz = __ldg(gp + Dm); gin = __ldg(gp + 2 * Dm);
            hold = __ldcg(&Hc[(d0 + dloc) * BPG + gb]);
        }

        // fill hA/hB (deinterleave global [k][4]; 8KB once per step)
#pragma unroll
        for (int r = 0; r < 2; ++r) {
            int k = tid + r * NTHR;
            float4 vv;
            asm volatile("ld.global.cg.v4.f32 {%0,%1,%2,%3}, [%4];"
                         : "=f"(vv.x), "=f"(vv.y), "=f"(vv.z), "=f"(vv.w)
                         : "l"(&Hc[k * BPG]));
            hA[k] = make_float2(vv.x, vv.y);
            hB[k] = make_float2(vv.z, vv.w);
        }
        __syncthreads();

        // k-loop: registers x SMEM-h, FFMA2
        unsigned long long accA[6], accB[6];
#pragma unroll
        for (int i = 0; i < 6; ++i) { accA[i] = 0ull; accB[i] = 0ull; }

#pragma unroll
        for (int j = 0; j < 16; ++j) {
            int k = lane + 32 * j;
            unsigned long long ha = *(const unsigned long long*)&hA[k];
            unsigned long long hb = *(const unsigned long long*)&hB[k];
#pragma unroll
            for (int i = 0; i < 6; ++i)
                ffma2_dual(accA[i], accB[i], w[i][j], ha, hb);
        }

        // reduce over lanes: xor16, xor8 -> lanes 0-7 hold 8-way partials
        float pA0[6], pA1[6], pB0[6], pB1[6];
#pragma unroll
        for (int i = 0; i < 6; ++i) {
            asm("mov.b64 {%0,%1}, %2;" : "=f"(pA0[i]), "=f"(pA1[i]) : "l"(accA[i]));
            asm("mov.b64 {%0,%1}, %2;" : "=f"(pB0[i]), "=f"(pB1[i]) : "l"(accB[i]));
            pA0[i] += __shfl_xor_sync(0xffffffffu, pA0[i], 16);
            pA1[i] += __shfl_xor_sync(0xffffffffu, pA1[i], 16);
            pB0[i] += __shfl_xor_sync(0xffffffffu, pB0[i], 16);
            pB1[i] += __shfl_xor_sync(0xffffffffu, pB1[i], 16);
            pA0[i] += __shfl_xor_sync(0xffffffffu, pA0[i], 8);
            pA1[i] += __shfl_xor_sync(0xffffffffu, pA1[i], 8);
            pB0[i] += __shfl_xor_sync(0xffffffffu, pB0[i], 8);
            pB1[i] += __shfl_xor_sync(0xffffffffu, pB1[i], 8);
        }
        if (lane < 8) {
#pragma unroll
            for (int i = 0; i < 6; ++i) {
                int cc = 6 * warp + i;
                red[(cc * BPG + 0) * 8 + lane] = pA0[i];
                red[(cc * BPG + 1) * 8 + lane] = pA1[i];
                red[(cc * BPG + 2) * 8 + lane] = pB0[i];
                red[(cc * BPG + 3) * 8 + lane] = pB1[i];
            }
        }
        __syncthreads();

        // gates (64 threads: 16 dims x 4 batches)
        if (tid < 64) {
            float gh[3];
#pragma unroll
            for (int g3 = 0; g3 < 3; ++g3) {
                const float* rp = &red[((g3 * 16 + dloc) * BPG + gb) * 8];
                float s = 0.f;
#pragma unroll
                for (int l = 0; l < 8; ++l) s += rp[l];
                gh[g3] = s;
            }
            float r = 1.f / (1.f + __expf(-(gir + gh[0])));
            float z = 1.f / (1.f + __expf(-(giz + gh[1])));
            float n = tanhf(gin + r * (gh[2] + my_bhn));
            float hnew = (1.f - z) * n + z * hold;
            Hn[(d0 + dloc) * BPG + gb] = hnew;
            g_rnn[((size_t)(b0 + gb) * Sm + t) * Dm + d0 + dloc] = hnew;
        }
        __syncthreads();

        // per-group barrier (single monotone counter + poll)
        target += GCTA;
        if (tid == 0) {
            __threadfence();
            atomicAdd(cnt, 1u);
            while (ld_acq(cnt) < target) { }
        }
        __syncthreads();
    }
}

// ---------------------------------------------------------------------------
extern "C" void kernel_launch(void* const* d_in, const int* in_sizes, int n_in,
                              void* d_out, int out_size)
{
    const float* x   = (const float*)d_in[0];
    const float* Wi  = (const float*)d_in[1];
    const float* bi  = (const float*)d_in[2];
    const float* Wh  = (const float*)d_in[3];
    const float* bhn = (const float*)d_in[4];
    const float* Wo  = (const float*)d_in[5];
    const float* bo  = (const float*)d_in[6];
    float* out = (float*)d_out;

    void* gi_ptr = nullptr;
    void* rnn_ptr = nullptr;
    cudaGetSymbolAddress(&gi_ptr, g_gi);
    cudaGetSymbolAddress(&rnn_ptr, g_rnn);

    init_state<<<32, 256>>>();

    dim3 g1(G3 / 64, (Bm_ * Sm) / 128);
    tf32_gemm_bias<<<g1, 256>>>(x, Wi, bi, (float*)gi_ptr, Bm_ * Sm, G3, Dm);

    gru_scan<<<NBLK, NTHR>>>(Wh, bhn);

    dim3 g2(Dm / 64, (Bm_ * Sm) / 128);
    tf32_gemm_bias<<<g2, 256>>>((const float*)rnn_ptr, Wo, bo, out, Bm_ * Sm, Dm, Dm);
}